// round 17
// baseline (speedup 1.0000x reference)
#include <cuda_runtime.h>
#include <cstdint>
#include <cstddef>

constexpr int B=256, T=64, H=512, S=32, C=32, A_=32, E=1024, BS=256;
constexpr int D=2048, X3H=1536, INX=1056, G3=768, NG=6144, DE_IN=3072, SC=1024;
constexpr int NBLK=296, NTH=256;

__device__ __align__(16) float g_deter[B*D];
__device__ __align__(16) float g_WinT [INX*X3H];  // W_in transposed [c][j]
__device__ __align__(16) float g_x   [B*X3H];     // x final (silu'd, biased)
__device__ int   g_sidx[B*S];                     // sampled idx (-1 = masked)
__device__ __align__(16) float g_hp  [8*B*D];     // h partials NEXT step (split8, masked)
__device__ __align__(16) float g_gip [3*B*NG];    // gi partials (split3, raw)
__device__ __align__(16) float g_gh  [B*NG];      // gh (biased)
__device__ __align__(16) float g_dein[B*DE_IN];
__device__ __align__(16) float g_h1  [6*2*B*H];   // M=512 (prior:4 slabs | post:6 slabs)
__device__ __align__(16) float g_h2  [4*2*B*H];   // split4 raw
__device__ __align__(16) float g_lp  [4*2*B*SC];  // logits partials (split4 raw)
__device__ __align__(16) float g_WprojT[DE_IN*D]; // W_proj^T  [k'][n]
__device__ __align__(16) float g_W1p [H*DE_IN];   // W1@W_proj [j][k']
__device__ __align__(16) float g_b1p [H];         // W1@b_proj + b1
__device__ unsigned g_cnt;
__device__ unsigned g_gen;
__device__ unsigned g_ctr[6*T + 1];

// ----------------------------- grid barrier --------------------------------
__device__ __forceinline__ void gridbar() {
  __syncthreads();
  if (threadIdx.x == 0) {
    unsigned gen = *(volatile unsigned*)&g_gen;
    __threadfence();
    if (atomicAdd(&g_cnt, 1u) == gridDim.x - 1u) {
      g_cnt = 0u;
      __threadfence();
      atomicExch(&g_gen, gen + 1u);
    } else {
      while (*(volatile unsigned*)&g_gen == gen) {}
    }
    __threadfence();
  }
  __syncthreads();
}

// ------------------------------ threefry2x32 -------------------------------
__device__ __forceinline__ void threefry(uint32_t k0, uint32_t k1, uint32_t x0,
                                         uint32_t x1, uint32_t& o0, uint32_t& o1) {
  uint32_t ks2 = 0x1BD11BDAu ^ k0 ^ k1;
#define TFR(x,r) x = (x<<r)|(x>>(32-r))
#define TF4(a,b,c,d) x0+=x1;TFR(x1,a);x1^=x0; x0+=x1;TFR(x1,b);x1^=x0; x0+=x1;TFR(x1,c);x1^=x0; x0+=x1;TFR(x1,d);x1^=x0;
  x0 += k0; x1 += k1;
  TF4(13,15,26,6);  x0 += k1;  x1 += ks2 + 1u;
  TF4(17,29,16,24); x0 += ks2; x1 += k0 + 2u;
  TF4(13,15,26,6);  x0 += k0;  x1 += k1 + 3u;
  TF4(17,29,16,24); x0 += k1;  x1 += ks2 + 4u;
  TF4(13,15,26,6);  x0 += ks2; x1 += k0 + 5u;
  o0 = x0; o1 = x1;
#undef TF4
#undef TFR
}

__device__ __forceinline__ float silu1(float v) { return v/(1.0f+expf(-v)); }

// ------------------------------ GEMM tile 128x64 ---------------------------
// Double-buffered smem pipeline; one __syncthreads per 16-k chunk.
// Aeff: NP=1 plain A0; NP>=2: (sum of NP partials)+Abias, optional SiLU.
// 256 threads, per-thread 8 rows x 4 cols. WMODE 0:+bias; 1:raw.
template <int NP,int SILU,int WMODE,int MASKED>
__device__ __forceinline__ void gemm(
    const float* __restrict__ A0, size_t pstr,
    const float* __restrict__ Abias, int lda,
    const float* __restrict__ W, int ldw, const float* __restrict__ bias,
    float* __restrict__ Cb, int ldc,
    int IN2, int kbase, int m0, int n0, int aColBase,
    const int* __restrict__ isf, int mt,
    float (*As)[16][136], float (*Ws)[16][68], float* mrow) {
  const int tid = threadIdx.x;
  if (MASKED) { if (tid < 128) mrow[tid] = isf[(size_t)(m0+tid)*T + mt] ? 0.0f : 1.0f; }
  __syncthreads();
  const int aoff = aColBase + kbase;
  const float* Ab0 = A0 + (size_t)m0*lda + aoff;
  const float* Wb  = W + (size_t)n0*ldw + kbase;
  const int alr = tid>>1, alq = (tid&1)<<3;
  const int wlr = tid>>2, wlq = (tid&3)<<2;
  const int ty = tid>>4, tx = tid&15;
  float acc[8][4] = {};
  float4 av0, av1, wv;

#define LOADCHUNK(KO) do {                                                   \
    size_t ao = (size_t)alr*lda + (KO) + alq;                                \
    av0 = *(const float4*)(Ab0 + ao);                                        \
    av1 = *(const float4*)(Ab0 + ao + 4);                                    \
    if (NP>=2) {                                                             \
      _Pragma("unroll")                                                      \
      for (int p = 1; p < NP; p++) {                                         \
        float4 b0v = *(const float4*)(Ab0 + p*pstr + ao);                    \
        float4 b1v = *(const float4*)(Ab0 + p*pstr + ao + 4);                \
        av0.x += b0v.x; av0.y += b0v.y; av0.z += b0v.z; av0.w += b0v.w;      \
        av1.x += b1v.x; av1.y += b1v.y; av1.z += b1v.z; av1.w += b1v.w;      \
      }                                                                      \
      float4 ab0 = *(const float4*)(Abias + aoff + (KO) + alq);              \
      float4 ab1 = *(const float4*)(Abias + aoff + (KO) + alq + 4);          \
      av0.x += ab0.x; av0.y += ab0.y; av0.z += ab0.z; av0.w += ab0.w;        \
      av1.x += ab1.x; av1.y += ab1.y; av1.z += ab1.z; av1.w += ab1.w;        \
      if (SILU) {                                                            \
        av0.x=silu1(av0.x); av0.y=silu1(av0.y);                              \
        av0.z=silu1(av0.z); av0.w=silu1(av0.w);                              \
        av1.x=silu1(av1.x); av1.y=silu1(av1.y);                              \
        av1.z=silu1(av1.z); av1.w=silu1(av1.w);                              \
      }                                                                      \
    }                                                                        \
    if (MASKED) {                                                            \
      float mm = mrow[alr];                                                  \
      av0.x*=mm; av0.y*=mm; av0.z*=mm; av0.w*=mm;                            \
      av1.x*=mm; av1.y*=mm; av1.z*=mm; av1.w*=mm;                            \
    }                                                                        \
    wv = *(const float4*)(Wb + (size_t)wlr*ldw + (KO) + wlq);                \
  } while(0)

#define STORECHUNK(BUF) do {                                                 \
    As[BUF][alq+0][alr]=av0.x; As[BUF][alq+1][alr]=av0.y;                    \
    As[BUF][alq+2][alr]=av0.z; As[BUF][alq+3][alr]=av0.w;                    \
    As[BUF][alq+4][alr]=av1.x; As[BUF][alq+5][alr]=av1.y;                    \
    As[BUF][alq+6][alr]=av1.z; As[BUF][alq+7][alr]=av1.w;                    \
    Ws[BUF][wlq+0][wlr]=wv.x; Ws[BUF][wlq+1][wlr]=wv.y;                      \
    Ws[BUF][wlq+2][wlr]=wv.z; Ws[BUF][wlq+3][wlr]=wv.w;                      \
  } while(0)

  LOADCHUNK(0);
  STORECHUNK(0);
  __syncthreads();
  int buf = 0;
  for (int k0 = 0; k0 < IN2; k0 += 16) {
    const bool more = (k0 + 16 < IN2);
    if (more) LOADCHUNK(k0 + 16);
#pragma unroll
    for (int kk = 0; kk < 16; kk++) {
      float4 a0 = *(const float4*)&As[buf][kk][ty<<3];
      float4 a1 = *(const float4*)&As[buf][kk][(ty<<3)+4];
      float4 w  = *(const float4*)&Ws[buf][kk][tx<<2];
      float am[8] = {a0.x,a0.y,a0.z,a0.w,a1.x,a1.y,a1.z,a1.w};
#pragma unroll
      for (int r = 0; r < 8; r++) {
        acc[r][0]+=am[r]*w.x; acc[r][1]+=am[r]*w.y;
        acc[r][2]+=am[r]*w.z; acc[r][3]+=am[r]*w.w;
      }
    }
    if (more) STORECHUNK(buf^1);
    __syncthreads();
    buf ^= 1;
  }
#undef LOADCHUNK
#undef STORECHUNK
#pragma unroll
  for (int r = 0; r < 8; r++) {
    int mi = m0 + (ty<<3) + r;
    int nb = n0 + (tx<<2);
    float4 v;
    v.x=acc[r][0]; v.y=acc[r][1]; v.z=acc[r][2]; v.w=acc[r][3];
    if (WMODE==0) {
      float4 bv = *(const float4*)(bias + nb);
      v.x+=bv.x; v.y+=bv.y; v.z+=bv.z; v.w+=bv.w;
    }
    *(float4*)(Cb + (size_t)mi*ldc + nb) = v;
  }
}

// ------------------------------ megakernel ---------------------------------
__global__ void __launch_bounds__(NTH, 2) k_rssm(
    const float* __restrict__ embed, const float* __restrict__ actions,
    const int* __restrict__ isf,
    const float* __restrict__ W_in,  const float* __restrict__ b_in,
    const float* __restrict__ W_blk, const float* __restrict__ b_blk,
    const float* __restrict__ W_ih,  const float* __restrict__ b_ih,
    const float* __restrict__ W_hh,  const float* __restrict__ b_hh,
    const float* __restrict__ W1,    const float* __restrict__ b1,
    const float* __restrict__ W2,    const float* __restrict__ b2,
    const float* __restrict__ W3,    const float* __restrict__ b3,
    const float* __restrict__ W_proj,const float* __restrict__ b_proj,
    float* __restrict__ out_deter, float* __restrict__ out_stoch,
    float* __restrict__ out_prior, float* __restrict__ out_post) {
  __shared__ __align__(16) float As[2][16][136];
  __shared__ __align__(16) float Ws[2][16][68];
  __shared__ float mrow[128];
  __shared__ int s_tl;
  const int bid = blockIdx.x;
  const int tid = threadIdx.x;
  const int gtid = bid*NTH + tid;
  const int gstep = gridDim.x*NTH;
  const int nwarp = gridDim.x*(NTH/32);
  const int wid = bid*(NTH/32) + (tid>>5);
  const int lane = tid & 31;
  const float TINYF = 1.17549435e-38f;
  const float UNIADD = (float)(0.01/32.0);
  const size_t PBD = (size_t)B*D;
  const size_t PBG = (size_t)B*NG;
  const size_t PBH = (size_t)2*B*H;
  const size_t PBL = (size_t)2*B*SC;

#define POP(pid) ({ if (tid==0) s_tl = (int)atomicAdd(&g_ctr[pid], 1u); \
                    __syncthreads(); int _v = s_tl; _v; })

// hnext tile i (0..511): p=i/64, spatial=i%64 -> m0=(sp/32)<<7, n0=(sp&31)<<6
#define HNEXT_TILE(i) do {                                                   \
    int _p = (i)>>6, _sp = (i)&63;                                           \
    gemm<1,0,1,1>(g_deter, 0, 0, D, W_blk, D, 0,                             \
                  g_hp + _p*PBD, D, D/8, _p*(D/8),                           \
                  (_sp>>5)<<7, (_sp&31)<<6, 0, isf, t+1, As, Ws, mrow);      \
  } while(0)

  // ---- init ----
  for (int i = gtid; i < 6*T + 1; i += gstep) g_ctr[i] = 0u;
  for (int i = gtid; i < B*D; i += gstep) g_deter[i] = 0.0f;
  for (size_t i = gtid; i < 8*PBD; i += gstep) g_hp[i] = 0.0f;   // h for t=0
  for (int i = gtid; i < B*S; i += gstep) g_sidx[i] = -1;        // stoch0 = 0
  for (size_t i = gtid; i < (size_t)INX*X3H; i += gstep) {       // W_in transpose
    int c = (int)(i / X3H), j = (int)(i - (size_t)c*X3H);
    g_WinT[i] = W_in[(size_t)j*INX + c];
  }
  for (size_t i = gtid; i < (size_t)DE_IN*D; i += gstep) {       // W_proj transpose
    int kp = (int)(i / D), n = (int)(i - (size_t)kp*D);
    g_WprojT[i] = W_proj[(size_t)n*DE_IN + kp];
  }
  if (gtid < H) {                                                // b1p = W1@b_proj + b1
    float s = b1[gtid];
    const float* wr = W1 + (size_t)gtid*D;
    for (int d = 0; d < D; d++) s += wr[d]*b_proj[d];
    g_b1p[gtid] = s;
  }
  gridbar();
  // W1p = W1 @ W_proj  (192 tiles, K=2048, raw)
  for (;;) {
    int tl = POP(6*T); if (tl >= 192) break;
    gemm<1,0,1,0>(W1, 0, 0, D, g_WprojT, D, 0, g_W1p, DE_IN,
                  D, 0, (tl/48)<<7, (tl%48)<<6, 0, 0, 0, As, Ws, mrow);
  }
  gridbar();

  for (int t = 0; t < T; t++) {
    const int hlive = (t + 1 < T) ? 1 : 0;
    // P1a: x = silu(b_in + one-hot gather + W_in_act@action)
    for (int q = gtid; q < B*(X3H/4); q += gstep) {
      int b = q/(X3H/4), j = (q - b*(X3H/4))*4;
      float4 acc = *(const float4*)(b_in + j);
      const int* idxp = g_sidx + b*S;
#pragma unroll 4
      for (int s = 0; s < S; s++) {
        int c = idxp[s];
        if (c >= 0) {
          float4 wv = *(const float4*)(g_WinT + (size_t)(s*C + c)*X3H + j);
          acc.x+=wv.x; acc.y+=wv.y; acc.z+=wv.z; acc.w+=wv.w;
        }
      }
      const float* act = actions + ((size_t)b*T + t)*A_;
#pragma unroll 4
      for (int a = 0; a < A_; a++) {
        float fa = act[a];
        float4 wv = *(const float4*)(g_WinT + (size_t)(SC + a)*X3H + j);
        acc.x+=fa*wv.x; acc.y+=fa*wv.y; acc.z+=fa*wv.z; acc.w+=fa*wv.w;
      }
      acc.x=silu1(acc.x); acc.y=silu1(acc.y); acc.z=silu1(acc.z); acc.w=silu1(acc.w);
      *(float4*)(g_x + (size_t)b*X3H + j) = acc;
    }
    // P1b: gh = (sum8 hp + b_blk)@W_hh + b_hh  (192 tiles x 16ch, blockdiag)
    for (;;) {
      int tl = POP(t*6+0); if (tl >= 192) break;
      int n0 = (tl%96)<<6;
      gemm<8,0,0,0>(g_hp, PBD, b_blk, D, W_hh, BS, b_hh,
                    g_gh, NG, BS, 0,
                    (tl/96)<<7, n0, (n0/G3)*BS, 0, 0, As, Ws, mrow);
    }
    gridbar();
    // P2: gi partials = x@W_ih  (split3: 576 tiles x 32ch)
    for (;;) {
      int tl = POP(t*6+1); if (tl >= 576) break;
      int p = tl/192, i = tl%192;
      gemm<1,0,1,0>(g_x, 0, 0, X3H, W_ih, X3H, 0,
                    g_gip + p*PBG, NG, X3H/3, p*(X3H/3),
                    (i/96)<<7, (i%96)<<6, 0, 0, 0, As, Ws, mrow);
    }
    gridbar();
    // P3: GRU combine -> deter/out_deter/dein ; embed -> dein
    for (int i = gtid; i < B*D; i += gstep) {
      int b = i>>11, d = i & (D-1), k = d>>8, g = d & (BS-1);
      size_t base = (size_t)b*NG + k*G3 + g;
      float ir = (g_gip[base]      + g_gip[PBG+base])      + g_gip[2*PBG+base]      + b_ih[k*G3+g];
      float iz = (g_gip[base+BS]   + g_gip[PBG+base+BS])   + g_gip[2*PBG+base+BS]   + b_ih[k*G3+g+BS];
      float inn= (g_gip[base+2*BS] + g_gip[PBG+base+2*BS]) + g_gip[2*PBG+base+2*BS] + b_ih[k*G3+g+2*BS];
      float hr=g_gh[base], hz=g_gh[base+BS], hnn=g_gh[base+2*BS];
      float hv = b_blk[d];
#pragma unroll
      for (int p = 0; p < 8; p++) hv += g_hp[p*PBD + i];
      float r = 1.0f/(1.0f+expf(-(ir+hr)));
      float z = 1.0f/(1.0f+expf(-(iz+hz)));
      float n = tanhf(inn + r*hnn);
      float dv = (1.0f - z)*n + z*hv;
      g_deter[i] = dv;
      g_dein[(size_t)b*DE_IN + d] = dv;
      out_deter[((size_t)b*T+t)*D + d] = dv;
    }
    for (int i = gtid; i < B*E; i += gstep) {
      int b = i>>10, j = i & (E-1);
      g_dein[(size_t)b*DE_IN + D + j] = embed[((size_t)b*T+t)*E + j];
    }
    gridbar();
    // P4': h1prior = deter@W1 (split4: 64 x 32ch)
    //      h1post  = dein@W1p (split6: 96 x 32ch)
    //      hnext tiles 0..169 (16ch)
    {
      int nP4 = 160 + hlive*170;
      for (;;) {
        int tl = POP(t*6+2); if (tl >= nP4) break;
        if (tl < 64) {
          int p = tl/16, i = tl%16;
          gemm<1,0,1,0>(g_deter, 0, 0, D, W1, D, 0, g_h1 + p*PBH, H,
                        D/4, p*(D/4), (i/8)<<7, (i%8)<<6, 0, 0, 0, As, Ws, mrow);
        } else if (tl < 160) {
          int j = tl-64, p = j/16, i = j%16;
          gemm<1,0,1,0>(g_dein - (size_t)256*DE_IN, 0, 0, DE_IN,
                        g_W1p, DE_IN, 0, g_h1 + p*PBH, H,
                        DE_IN/6, p*(DE_IN/6), 256 + ((i/8)<<7), (i%8)<<6,
                        0, 0, 0, As, Ws, mrow);
        } else {
          int i = tl-160;
          HNEXT_TILE(i);
        }
      }
    }
    gridbar();
    // P5': hnext tiles 170..369 first (heavy, 16ch), then h2 (128 x 8ch)
    {
      int nh = hlive*200;
      int nP5 = 128 + nh;
      for (;;) {
        int tl = POP(t*6+3); if (tl >= nP5) break;
        if (tl < nh) {
          HNEXT_TILE(170 + tl);
        } else {
          int j = tl - nh;
          int p = j/32, i = j%32;
          int m0 = (i/8)<<7, n0 = (i%8)<<6;
          if (m0 < 256)
            gemm<4,1,1,0>(g_h1, PBH, b1, H, W2, H, 0,
                          g_h2 + p*PBH, H, H/4, p*(H/4), m0, n0, 0, 0, 0, As, Ws, mrow);
          else
            gemm<6,1,1,0>(g_h1, PBH, g_b1p, H, W2, H, 0,
                          g_h2 + p*PBH, H, H/4, p*(H/4), m0, n0, 0, 0, 0, As, Ws, mrow);
        }
      }
    }
    gridbar();
    // P6': hnext tiles 370..511 first (16ch), then logits (256 x 8ch)
    {
      int nh = hlive*142;
      int nP6 = 256 + nh;
      for (;;) {
        int tl = POP(t*6+4); if (tl >= nP6) break;
        if (tl < nh) {
          HNEXT_TILE(370 + tl);
        } else {
          int j = tl - nh;
          int p = j/64, i = j%64;
          gemm<4,1,1,0>(g_h2, PBH, b2, H, W3, H, 0,
                        g_lp + p*PBL, SC, H/4, p*(H/4),
                        (i/16)<<7, (i%16)<<6, 0, 0, 0, As, Ws, mrow);
        }
      }
    }
    gridbar();
    // P8: prior combine -> out_prior ; sample(post combine) -> out_post/stoch/sidx
    for (int i = gtid; i < B*SC; i += gstep) {
      int b = i>>10, j = i & (SC-1);
      out_prior[((size_t)b*T+t)*SC + j] =
        ((g_lp[i] + g_lp[PBL+i]) + (g_lp[2*PBL+i] + g_lp[3*PBL+i])) + b3[j];
    }
    {
      uint32_t k0, k1;
      threefry(0u, 42u, 0u, (uint32_t)t, k0, k1);   // fold_in(key(42), t)
      for (int gw = wid; gw < 128*32; gw += nwarp) {
        int b0 = gw >> 5, s = gw & 31;
        uint32_t nA = (uint32_t)(b0*SC + s*C + lane);
        uint32_t a0,a1,c0,c1;
        threefry(k0,k1,0u,nA,a0,a1);
        threefry(k0,k1,0u,nA + (uint32_t)(128*SC),c0,c1);
        uint32_t bitsH[2] = { a0^a1, c0^c1 };
#pragma unroll
        for (int half = 0; half < 2; half++) {
          int b = b0 + half*128;
          size_t li = (size_t)(256+b)*SC + s*C + lane;
          float lg = ((g_lp[li] + g_lp[PBL+li]) + (g_lp[2*PBL+li] + g_lp[3*PBL+li]))
                     + b3[s*C + lane];
          out_post[((size_t)b*T+t)*SC + s*C + lane] = lg;
          float m = lg;
          for (int o = 16; o; o >>= 1) m = fmaxf(m, __shfl_xor_sync(~0u, m, o));
          float e = expf(lg - m), sum = e;
          for (int o = 16; o; o >>= 1) sum += __shfl_xor_sync(~0u, sum, o);
          float p = 0.99f*(e/sum) + UNIADD;
          float uf = __uint_as_float((bitsH[half]>>9) | 0x3f800000u) - 1.0f;
          uf = fmaxf(uf + TINYF, TINYF);
          float val = -logf(-logf(uf)) + logf(p);
          float bv = val; int bidx = lane;
          for (int o = 16; o; o >>= 1) {
            float ov = __shfl_xor_sync(~0u, bv, o);
            int   oi = __shfl_xor_sync(~0u, bidx, o);
            if (ov > bv || (ov == bv && oi < bidx)) { bv = ov; bidx = oi; }
          }
          float oneh = (lane == bidx) ? 1.0f : 0.0f;
          out_stoch[((size_t)b*T+t)*SC + s*C + lane] = oneh;
          if (lane == 0 && t + 1 < T)
            g_sidx[(size_t)b*S + s] = isf[(size_t)b*T + t + 1] ? -1 : bidx;
        }
      }
    }
    gridbar();
  }
#undef POP
#undef HNEXT_TILE
}

extern "C" void kernel_launch(void* const* d_in, const int* in_sizes, int n_in,
                              void* d_out, int out_size) {
  const float* embed  =(const float*)d_in[0];
  const float* actions=(const float*)d_in[1];
  const int*   isf    =(const int*)  d_in[2];
  const float* W_in =(const float*)d_in[5],  *b_in =(const float*)d_in[6];
  const float* W_blk=(const float*)d_in[7],  *b_blk=(const float*)d_in[8];
  const float* W_ih =(const float*)d_in[9],  *b_ih =(const float*)d_in[10];
  const float* W_hh =(const float*)d_in[11], *b_hh =(const float*)d_in[12];
  const float* W1   =(const float*)d_in[13], *b1   =(const float*)d_in[14];
  const float* W2   =(const float*)d_in[15], *b2   =(const float*)d_in[16];
  const float* W3   =(const float*)d_in[17], *b3   =(const float*)d_in[18];
  const float* W_proj=(const float*)d_in[19],*b_proj=(const float*)d_in[20];

  float* out = (float*)d_out;
  float* out_deter = out;                          // [B,T,D]
  float* out_stoch = out + (size_t)B*T*D;          // [B,T,S,C]
  float* out_prior = out_stoch + (size_t)B*T*SC;   // [B,T,S,C]
  float* out_post  = out_prior + (size_t)B*T*SC;   // [B,T,S,C]

  k_rssm<<<NBLK, NTH>>>(embed, actions, isf,
                        W_in, b_in, W_blk, b_blk, W_ih, b_ih, W_hh, b_hh,
                        W1, b1, W2, b2, W3, b3, W_proj, b_proj,
                        out_deter, out_stoch, out_prior, out_post);
}